// round 3
// baseline (speedup 1.0000x reference)
#include <cuda_runtime.h>
#include <cuda_bf16.h>
#include <cstdint>

// Problem constants
#define TT   512
#define BB   64
#define HID  1024
#define LAY  4
#define NWAVE (TT + LAY - 1)   // 515

// Hidden-state ring: 2 wave slots x [L][B][H] fp32 = 2 MB (L2 resident)
__device__ float g_ring[2][LAY][BB][HID];

// Packed split-bf16 weights, CTA-slab-contiguous layout:
// [m = l*2+phase][cb 0..31][kc 0..63][gg 0..2][row_local 0..31][tig 0..3] -> uint4
// uint4 = {hi(k0,k1), hi(k8,k9), lo(k0,k1), lo(k8,k9)}
// slab per (m,cb,kc) = 3*32*4*16B = 6144 B, contiguous.  Total 100.7 MB.
#define SLAB_U4 384            // 6144 bytes / 16
__device__ uint4 g_wpack[8ull * 32 * 64 * SLAB_U4];

// ---------- dynamic smem layout ----------
struct __align__(16) SmemLayout {
    uint64_t full[2][4];      // [stream][stage]
    uint64_t empty[2][4];
    uint4    buf[2][4][SLAB_U4];   // 2 streams x 4 stages x 6KB = 48 KB
    float    red[8][32][32];       // K-split reduction exchange (32 KB)
};

// ---------- helpers ----------
__device__ __forceinline__ uint32_t smem_u32(const void* p) {
    uint32_t a;
    asm("{ .reg .u64 t; cvta.to.shared.u64 t, %1; cvt.u32.u64 %0, t; }" : "=r"(a) : "l"(p));
    return a;
}

__device__ __forceinline__ void mbar_init(uint32_t mbar, uint32_t cnt) {
    asm volatile("mbarrier.init.shared.b64 [%0], %1;" :: "r"(mbar), "r"(cnt) : "memory");
}

__device__ __forceinline__ void mbar_arrive(uint32_t mbar) {
    asm volatile("mbarrier.arrive.shared.b64 _, [%0];" :: "r"(mbar) : "memory");
}

__device__ __forceinline__ void mbar_wait(uint32_t mbar, uint32_t parity) {
    uint32_t done;
    asm volatile(
        "{\n\t.reg .pred p;\n\t"
        "mbarrier.try_wait.parity.acquire.cta.shared::cta.b64 p, [%1], %2;\n\t"
        "selp.b32 %0, 1, 0, p;\n\t}"
        : "=r"(done) : "r"(mbar), "r"(parity) : "memory");
    while (!done) {
        asm volatile(
            "{\n\t.reg .pred p;\n\t"
            "mbarrier.try_wait.parity.acquire.cta.shared::cta.b64 p, [%1], %2, 0x989680;\n\t"
            "selp.b32 %0, 1, 0, p;\n\t}"
            : "=r"(done) : "r"(mbar), "r"(parity) : "memory");
    }
}

__device__ __forceinline__ void issue_copy(uint32_t dst_smem, const uint4* src, uint32_t mbar) {
    asm volatile("mbarrier.arrive.expect_tx.shared.b64 _, [%0], %1;"
                 :: "r"(mbar), "r"(6144u) : "memory");
    asm volatile("cp.async.bulk.shared::cluster.global.mbarrier::complete_tx::bytes "
                 "[%0], [%1], %2, [%3];"
                 :: "r"(dst_smem), "l"(src), "r"(6144u), "r"(mbar) : "memory");
}

__device__ __forceinline__ void split_pair(float x, float y, uint32_t& hi, uint32_t& lo) {
    __nv_bfloat16 hx = __float2bfloat16(x);
    __nv_bfloat16 hy = __float2bfloat16(y);
    float rx = x - __bfloat162float(hx);
    float ry = y - __bfloat162float(hy);
    __nv_bfloat162 H2; H2.x = hx; H2.y = hy;
    __nv_bfloat162 L2 = __floats2bfloat162_rn(rx, ry);
    hi = *reinterpret_cast<uint32_t*>(&H2);
    lo = *reinterpret_cast<uint32_t*>(&L2);
}

__device__ __forceinline__ void mma_bf16(float* c, const uint32_t* a, uint32_t b0, uint32_t b1) {
    asm volatile(
        "mma.sync.aligned.m16n8k16.row.col.f32.bf16.bf16.f32 "
        "{%0,%1,%2,%3},{%4,%5,%6,%7},{%8,%9},{%0,%1,%2,%3};"
        : "+f"(c[0]), "+f"(c[1]), "+f"(c[2]), "+f"(c[3])
        : "r"(a[0]), "r"(a[1]), "r"(a[2]), "r"(a[3]), "r"(b0), "r"(b1));
}

// ---------- weight packing (new slab layout) ----------
__global__ void pack_weights_kernel(const float* __restrict__ w_ih,
                                    const float* __restrict__ w_hh) {
    int64_t idx = (int64_t)blockIdx.x * blockDim.x + threadIdx.x;
    const int64_t total = 8ll * 32 * 64 * SLAB_U4;
    if (idx >= total) return;
    int tig = (int)(idx & 3);
    int64_t t = idx >> 2;
    int row_local = (int)(t & 31); t >>= 5;
    int gg = (int)(t % 3);         t /= 3;
    int kc = (int)(t & 63);        t >>= 6;
    int cb = (int)(t & 31);
    int m  = (int)(t >> 5);
    int l = m >> 1, s = m & 1;
    int n = gg * HID + cb * 32 + row_local;
    const float* src = (s ? w_hh : w_ih) + ((int64_t)l * 3072 + n) * 1024 + kc * 16 + 2 * tig;
    float f0 = src[0], f1 = src[1], f2 = src[8], f3 = src[9];
    uint4 q;
    split_pair(f0, f1, q.x, q.z);
    split_pair(f2, f3, q.y, q.w);
    g_wpack[idx] = q;
}

// ---------- h0 init ----------
__global__ void init_h0_kernel(const float* __restrict__ h0) {
    int idx = blockIdx.x * blockDim.x + threadIdx.x;   // < L*B*H = 262144
    int l = idx >> 16;
    int rest = idx & 0xFFFF;
    int slot = (l + 1) & 1;                            // read-slot of wave l
    (&g_ring[slot][l][0][0])[rest] = h0[idx];
}

// ---------- wave kernel ----------
// grid = 128 (l = bx>>5, cb = bx&31), block = 512 threads (16 warps)
// warp = mstrip(0..3) x ksplit(0..1) x jhalf(0..1)
// stream s = ksplit: steps i=0..63 -> phase p=i>>5, kidx=i&31, kc = s*32 + kidx
__global__ void __launch_bounds__(512, 1)
wave_kernel(const float* __restrict__ x,
            const float* __restrict__ b_ih,
            const float* __restrict__ b_hh,
            int w) {
    int l  = blockIdx.x >> 5;
    int cb = blockIdx.x & 31;
    int t  = w - l;
    if (t < 0 || t >= TT) return;

    extern __shared__ uint8_t smem_raw[];
    SmemLayout* sm = reinterpret_cast<SmemLayout*>(smem_raw);

    const int rs = (w + 1) & 1;   // read slot
    const int ws = w & 1;         // write slot

    const float* inp   = (l == 0) ? (x + (int64_t)t * BB * HID) : &g_ring[rs][l - 1][0][0];
    const float* hprev = &g_ring[rs][l][0][0];
    float*       hout  = &g_ring[ws][l][0][0];

    const int lane = threadIdx.x & 31;
    const int warp = threadIdx.x >> 5;
    const int mstrip = warp & 3;
    const int ksplit = (warp >> 2) & 1;
    const int jhalf  = warp >> 3;
    const int gid = lane >> 2;    // 0..7
    const int tig = lane & 3;     // 0..3
    const int c0 = cb * 32;
    const int s = ksplit;

    // init barriers
    if (threadIdx.x == 0) {
#pragma unroll
        for (int st = 0; st < 2; ++st)
#pragma unroll
            for (int b = 0; b < 4; ++b) {
                mbar_init(smem_u32(&sm->full[st][b]), 1);
                mbar_init(smem_u32(&sm->empty[st][b]), 256);
            }
    }
    __syncthreads();

    uint32_t full_b[4], empty_b[4];
#pragma unroll
    for (int b = 0; b < 4; ++b) {
        full_b[b]  = smem_u32(&sm->full[s][b]);
        empty_b[b] = smem_u32(&sm->empty[s][b]);
    }

    // global slab base for this CTA/stream: index fn of step i
    // m = l*2 + (i>>5); kc = s*32 + (i&31)
    // offset_u4(i) = ((m*32 + cb)*64 + kc) * SLAB_U4
    const uint4* src0 = g_wpack + ((int64_t)((l * 2 + 0) * 32 + cb) * 64 + s * 32) * SLAB_U4;
    const uint4* src1 = g_wpack + ((int64_t)((l * 2 + 1) * 32 + cb) * 64 + s * 32) * SLAB_U4;

    const bool producer = (lane == 0) && (warp == s * 4);

    // prologue: issue slabs 0..2
    if (producer) {
#pragma unroll
        for (int j = 0; j < 3; ++j)
            issue_copy(smem_u32(&sm->buf[s][j][0]), src0 + (int64_t)j * SLAB_U4, full_b[j]);
    }

    // acc[group][jt_local][reg]; groups: 0=r, 1=z, 2=gi_n, 3=gh_n
    float acc[4][2][4];
#pragma unroll
    for (int g = 0; g < 4; ++g)
#pragma unroll
        for (int j = 0; j < 2; ++j)
#pragma unroll
            for (int r = 0; r < 4; ++r) acc[g][j][r] = 0.f;

    const int r0 = mstrip * 16 + gid;
    const int rl_base = (jhalf * 2) * 8 + gid;   // row_local for jtl=0

    // A prefetch for step 0
    float2 araw[4];
    {
        const float* ar0 = inp + (int64_t)r0 * HID + (s * 32) * 16 + 2 * tig;
        const float* ar1 = ar0 + 8 * HID;
        araw[0] = *(const float2*)(ar0);
        araw[1] = *(const float2*)(ar1);
        araw[2] = *(const float2*)(ar0 + 8);
        araw[3] = *(const float2*)(ar1 + 8);
    }

    for (int i = 0; i < 64; ++i) {
        const int p = i >> 5;
        const int stage = i & 3;

        // producer: issue slab i+3
        if (producer) {
            int j = i + 3;
            if (j < 64) {
                if (j >= 4) mbar_wait(empty_b[j & 3], ((j - 4) >> 2) & 1);
                const uint4* srcj = ((j >> 5) ? src1 : src0) + (int64_t)(j & 31) * SLAB_U4;
                issue_copy(smem_u32(&sm->buf[s][j & 3][0]), srcj, full_b[j & 3]);
            }
        }

        // split current A
        uint32_t Ah[4], Al[4];
#pragma unroll
        for (int q = 0; q < 4; ++q) split_pair(araw[q].x, araw[q].y, Ah[q], Al[q]);

        // prefetch next step's A (global, hides under MMAs)
        if (i < 63) {
            const int ni = i + 1;
            const int np = ni >> 5;
            const float* act = np ? hprev : inp;
            const float* ar0 = act + (int64_t)r0 * HID + (s * 32 + (ni & 31)) * 16 + 2 * tig;
            const float* ar1 = ar0 + 8 * HID;
            araw[0] = *(const float2*)(ar0);
            araw[1] = *(const float2*)(ar1);
            araw[2] = *(const float2*)(ar0 + 8);
            araw[3] = *(const float2*)(ar1 + 8);
        }

        // wait for slab i
        mbar_wait(full_b[stage], (i >> 2) & 1);

        const uint4* slab = &sm->buf[s][stage][0];
        const int g_third = p ? 3 : 2;

#pragma unroll
        for (int gg = 0; gg < 3; ++gg) {
            const int g = (gg < 2) ? gg : g_third;
#pragma unroll
            for (int jtl = 0; jtl < 2; ++jtl) {
                uint4 q = slab[((gg * 32 + rl_base + jtl * 8) << 2) + tig];
                float* C = acc[g][jtl];
                mma_bf16(C, Ah, q.x, q.y);   // Ah * Wh
                mma_bf16(C, Ah, q.z, q.w);   // Ah * Wl
                mma_bf16(C, Al, q.x, q.y);   // Al * Wh
            }
        }

        // release slab i
        mbar_arrive(empty_b[stage]);
    }

    // ---- cross-warp K reduction through smem ----
    __syncthreads();   // all pipeline traffic done; safe to reuse/order red
    if (ksplit == 1) {
        const float* af = &acc[0][0][0];
        float* dst = &sm->red[jhalf * 4 + mstrip][lane][0];
#pragma unroll
        for (int i = 0; i < 32; ++i) dst[i] = af[i];
    }
    __syncthreads();
    if (ksplit == 1) return;
    {
        float* af = &acc[0][0][0];
        const float* srcr = &sm->red[jhalf * 4 + mstrip][lane][0];
#pragma unroll
        for (int i = 0; i < 32; ++i) af[i] += srcr[i];
    }

    // ---- gates ----
    const float* bi = b_ih + l * 3 * HID;
    const float* bh = b_hh + l * 3 * HID;
#pragma unroll
    for (int jtl = 0; jtl < 2; ++jtl) {
        const int jbase = (jhalf * 2 + jtl) * 8 + tig * 2;
#pragma unroll
        for (int half = 0; half < 2; ++half) {
            const int b = mstrip * 16 + gid + half * 8;
#pragma unroll
            for (int par = 0; par < 2; ++par) {
                const int c = c0 + jbase + par;
                const int ri = half * 2 + par;
                float pr  = acc[0][jtl][ri] + bi[c]           + bh[c];
                float pz  = acc[1][jtl][ri] + bi[HID + c]     + bh[HID + c];
                float gin = acc[2][jtl][ri] + bi[2 * HID + c];
                float ghn = acc[3][jtl][ri] + bh[2 * HID + c];
                float rr = 1.f / (1.f + __expf(-pr));
                float zz = 1.f / (1.f + __expf(-pz));
                float nn = tanhf(gin + rr * ghn);
                float hp = hprev[(int64_t)b * HID + c];
                hout[(int64_t)b * HID + c] = (1.f - zz) * nn + zz * hp;
            }
        }
    }
}

// ---------- output copy ----------
__global__ void copy_out_kernel(float* __restrict__ out) {
    int idx = blockIdx.x * blockDim.x + threadIdx.x;   // < L*B*H
    int l = idx >> 16;
    int rest = idx & 0xFFFF;
    int slot = (TT - 1 + l) & 1;  // slot of layer l's final write (wave T-1+l)
    out[idx] = (&g_ring[slot][l][0][0])[rest];
}

// ---------- launch ----------
extern "C" void kernel_launch(void* const* d_in, const int* in_sizes, int n_in,
                              void* d_out, int out_size) {
    const float* x    = (const float*)d_in[0];
    const float* h0   = (const float*)d_in[1];
    const float* w_ih = (const float*)d_in[2];
    const float* w_hh = (const float*)d_in[3];
    const float* b_ih = (const float*)d_in[4];
    const float* b_hh = (const float*)d_in[5];
    float* out = (float*)d_out;

    const int smem_bytes = (int)sizeof(SmemLayout);
    cudaFuncSetAttribute(wave_kernel, cudaFuncAttributeMaxDynamicSharedMemorySize, smem_bytes);

    // 1) pack weights into slab-contiguous split-bf16 layout
    {
        int64_t total = 8ll * 32 * 64 * SLAB_U4;
        int thr = 256;
        int blks = (int)((total + thr - 1) / thr);
        pack_weights_kernel<<<blks, thr>>>(w_ih, w_hh);
    }
    // 2) place h0 into each layer's first read slot
    init_h0_kernel<<<(LAY * BB * HID) / 256, 256>>>(h0);

    // 3) wavefront: 515 dependent waves, stream-ordered
    for (int w = 0; w < NWAVE; ++w) {
        wave_kernel<<<128, 512, smem_bytes>>>(x, b_ih, b_hh, w);
    }

    // 4) gather final hidden states
    copy_out_kernel<<<(LAY * BB * HID) / 256, 256>>>(out);
}